// round 3
// baseline (speedup 1.0000x reference)
#include <cuda_runtime.h>
#include <cuda_bf16.h>
#include <cstdint>

// FP4(E2M1) weight-only linear via mma.sync bf16 HMMA.
// out[32,8192] = inp[32,8192] @ W[8192,8192]^T + bias
// W[n,k] = LUT(nibble)*scales[n,k/16]*amax.
// Strategy: MMA uses EXACT bf16 LUT values (unscaled); activations amax-folded
// and split hi/lo bf16 (2 MMA passes); per-16k-block scale applied in fp32.

#define TOKENS   32
#define NFEAT    8192
#define KFEAT    8192
#define NWIN     (KFEAT / 16)      // 512 scale blocks / mma k-steps
#define KSPLIT   2
#define WIN_PER_CTA (NWIN / KSPLIT)

__device__ uint4 g_bfrag[NWIN * 4 * 32];            // [win][group][lane] {bhi0,bhi1,blo0,blo1}
__device__ float g_part[KSPLIT * TOKENS * NFEAT];   // split-K partials

// decode packed byte -> bf16x2 {lut[high nib] | lut[low nib]} (exact, unscaled)
__device__ __forceinline__ uint32_t dec(uint32_t b){
    uint32_t sel = b & 0x77u;
    uint32_t h = __byte_perm(0x3F3F3F00u, 0x40404040u, sel);   // exponent bytes
    uint32_t l = __byte_perm(0xC0800000u, 0xC0804000u, sel);   // mantissa bytes
    uint32_t r = __byte_perm(l, h, 0x5140u);                   // [lo0,hi0,lo1,hi1]
    return r | ((b & 0x8u) << 12) | ((b & 0x80u) << 24);       // signs
}

__device__ __forceinline__ void mma16816(
    float& d0, float& d1, float& d2, float& d3,
    uint32_t a0, uint32_t a1, uint32_t a2, uint32_t a3,
    uint32_t b0, uint32_t b1,
    float c0, float c1, float c2, float c3)
{
    asm("mma.sync.aligned.m16n8k16.row.col.f32.bf16.bf16.f32 "
        "{%0,%1,%2,%3}, {%4,%5,%6,%7}, {%8,%9}, {%10,%11,%12,%13};"
        : "=f"(d0), "=f"(d1), "=f"(d2), "=f"(d3)
        : "r"(a0), "r"(a1), "r"(a2), "r"(a3), "r"(b0), "r"(b1),
          "f"(c0), "f"(c1), "f"(c2), "f"(c3));
}

__device__ __forceinline__ uint32_t pack_bf16x2(float lo, float hi){
    uint32_t r;
    asm("cvt.rn.bf16x2.f32 %0, %1, %2;" : "=r"(r) : "f"(hi), "f"(lo));
    return r;
}

// ---------------- prologue: build B fragments ----------------
// For window m, group g, lane: c=lane&3, n=g*8+(lane>>2), k0=16m+4c.
// Slot perm: b0 = k0,k0+1 (pair 8m+2c); b1 = k0+2,k0+3 (pair 8m+2c+1).
__global__ void bfrag_kernel(const float* __restrict__ inp, const float* __restrict__ amax){
    int id = blockIdx.x * blockDim.x + threadIdx.x;   // 0..65535
    int lane = id & 31;
    int g    = (id >> 5) & 3;
    int m    = id >> 7;
    int c    = lane & 3;
    int n    = g * 8 + (lane >> 2);
    int k0   = 16 * m + 4 * c;
    const float am = __ldg(amax);

    float4 a = *reinterpret_cast<const float4*>(inp + (size_t)n * KFEAT + k0);
    a.x *= am; a.y *= am; a.z *= am; a.w *= am;

    uint32_t bhi0 = pack_bf16x2(a.x, a.y);
    uint32_t bhi1 = pack_bf16x2(a.z, a.w);
    float r0 = a.x - __uint_as_float(bhi0 << 16);
    float r1 = a.y - __uint_as_float(bhi0 & 0xFFFF0000u);
    float r2 = a.z - __uint_as_float(bhi1 << 16);
    float r3 = a.w - __uint_as_float(bhi1 & 0xFFFF0000u);
    uint32_t blo0 = pack_bf16x2(r0, r1);
    uint32_t blo1 = pack_bf16x2(r2, r3);

    g_bfrag[id] = make_uint4(bhi0, bhi1, blo0, blo1);
}

// ---------------- main GEMM ----------------
// CTA: 256 thr = 8 warps; warp = 16 weight rows x 32 tokens.
// grid = (NFEAT/128, KSPLIT) = (64, 2)
__global__ void __launch_bounds__(256) fp4_hmma_kernel(
    const int*   __restrict__ qw,       // [N, K/2] one packed byte per int32
    const float* __restrict__ scales)   // [N, K/16]
{
    const int tid = threadIdx.x, wid = tid >> 5, lane = tid & 31;
    const int c  = lane & 3;
    const int r0 = blockIdx.x * 128 + wid * 16 + (lane >> 2);
    const int r8 = r0 + 8;
    const int wb = blockIdx.y * WIN_PER_CTA;   // window base for this K-split

    float acc[4][4];
    #pragma unroll
    for (int g = 0; g < 4; ++g)
        #pragma unroll
        for (int j = 0; j < 4; ++j) acc[g][j] = 0.f;

    const uint2* qrow0 = reinterpret_cast<const uint2*>(qw + (size_t)r0 * (KFEAT / 2));
    const uint2* qrow8 = reinterpret_cast<const uint2*>(qw + (size_t)r8 * (KFEAT / 2));
    const float* srow0 = scales + (size_t)r0 * NWIN;
    const float* srow8 = scales + (size_t)r8 * NWIN;

    for (int it = 0; it < WIN_PER_CTA / 4; ++it){
        const int mb = wb + it * 4;
        const float4 s0 = __ldg(reinterpret_cast<const float4*>(srow0 + mb));
        const float4 s8 = __ldg(reinterpret_cast<const float4*>(srow8 + mb));
        const float s0a[4] = {s0.x, s0.y, s0.z, s0.w};
        const float s8a[4] = {s8.x, s8.y, s8.z, s8.w};

        #pragma unroll
        for (int w = 0; w < 4; ++w){
            const int m = mb + w;
            // A fragment: pairs 8m+2c (slot c) and 8m+2c+1 (slot c+4), rows r0,r8
            const uint2 qa = __ldg(qrow0 + m * 4 + c);
            const uint2 qb = __ldg(qrow8 + m * 4 + c);
            const uint32_t a0 = dec(qa.x), a2 = dec(qa.y);
            const uint32_t a1 = dec(qb.x), a3 = dec(qb.y);
            const float sr = s0a[w], sr8 = s8a[w];

            #pragma unroll
            for (int g = 0; g < 4; ++g){
                const uint4 bf = __ldg(&g_bfrag[(size_t)(m * 4 + g) * 32 + lane]);
                float p0, p1, p2, p3;
                mma16816(p0, p1, p2, p3, a0, a1, a2, a3, bf.x, bf.y, 0.f, 0.f, 0.f, 0.f);
                mma16816(p0, p1, p2, p3, a0, a1, a2, a3, bf.z, bf.w, p0, p1, p2, p3);
                acc[g][0] = fmaf(sr,  p0, acc[g][0]);
                acc[g][1] = fmaf(sr,  p1, acc[g][1]);
                acc[g][2] = fmaf(sr8, p2, acc[g][2]);
                acc[g][3] = fmaf(sr8, p3, acc[g][3]);
            }
        }
    }

    // epilogue: D fragment (row r0/r8, token cols g*8 + 2c, 2c+1)
    float* base = g_part + (size_t)blockIdx.y * (TOKENS * NFEAT);
    #pragma unroll
    for (int g = 0; g < 4; ++g){
        const int t0 = g * 8 + 2 * c;
        base[(size_t)t0       * NFEAT + r0] = acc[g][0];
        base[(size_t)(t0 + 1) * NFEAT + r0] = acc[g][1];
        base[(size_t)t0       * NFEAT + r8] = acc[g][2];
        base[(size_t)(t0 + 1) * NFEAT + r8] = acc[g][3];
    }
}

// ---------------- reduce split-K + bias ----------------
__global__ void reduce_kernel(const float* __restrict__ bias, float* __restrict__ out){
    int i = blockIdx.x * blockDim.x + threadIdx.x;
    if (i >= TOKENS * NFEAT) return;
    out[i] = g_part[i] + g_part[TOKENS * NFEAT + i] + bias[i & (NFEAT - 1)];
}

extern "C" void kernel_launch(void* const* d_in, const int* in_sizes, int n_in,
                              void* d_out, int out_size)
{
    const float* inp    = (const float*)d_in[0];
    const int*   qw     = (const int*)  d_in[1];
    const float* scales = (const float*)d_in[2];
    const float* amax   = (const float*)d_in[3];
    const float* bias   = (const float*)d_in[4];
    float* out = (float*)d_out;

    bfrag_kernel<<<(NWIN * 4 * 32) / 256, 256>>>(inp, amax);

    dim3 grid(NFEAT / 128, KSPLIT);
    fp4_hmma_kernel<<<grid, 256>>>(qw, scales);

    reduce_kernel<<<(TOKENS * NFEAT + 255) / 256, 256>>>(bias, out);
}

// round 4
// speedup vs baseline: 3.0298x; 3.0298x over previous
#include <cuda_runtime.h>
#include <cuda_bf16.h>
#include <cstdint>

// FP4(E2M1) weight-only linear via mma.sync bf16 HMMA.
// out[32,8192] = inp[32,8192] @ W[8192,8192]^T + bias,  W[n,k]=LUT(nib)*scales[n,k/16]*amax
// MMA uses EXACT bf16 LUT values (unscaled); activations amax-folded and split
// hi/lo bf16 (2 MMA passes); per-16k-block scale applied in fp32 FFMA.

#define TOKENS   32
#define NFEAT    8192
#define KFEAT    8192
#define NWIN     (KFEAT / 16)          // 512 mma k-steps == scale blocks
#define KSPLIT   8
#define WIN_PER_CTA (NWIN / KSPLIT)    // 64

__device__ uint4 g_bfrag[NWIN * 4 * 32];            // [win][group][lane] {bhi0,bhi1,blo0,blo1}
__device__ float g_part[KSPLIT * TOKENS * NFEAT];   // split-K partials (8 MB)

// decode packed byte -> bf16x2 {lut[hi nib] | lut[lo nib]} (exact, unscaled)
__device__ __forceinline__ uint32_t dec(uint32_t b){
    uint32_t sel = b & 0x77u;
    uint32_t h = __byte_perm(0x3F3F3F00u, 0x40404040u, sel);   // exponent bytes
    uint32_t l = __byte_perm(0xC0800000u, 0xC0804000u, sel);   // mantissa bytes
    uint32_t r = __byte_perm(l, h, 0x5140u);                   // [lo0,hi0,lo1,hi1]
    return r | ((b & 0x8u) << 12) | ((b & 0x80u) << 24);       // signs
}

__device__ __forceinline__ void mma16816(
    float& d0, float& d1, float& d2, float& d3,
    uint32_t a0, uint32_t a1, uint32_t a2, uint32_t a3,
    uint32_t b0, uint32_t b1,
    float c0, float c1, float c2, float c3)
{
    asm("mma.sync.aligned.m16n8k16.row.col.f32.bf16.bf16.f32 "
        "{%0,%1,%2,%3}, {%4,%5,%6,%7}, {%8,%9}, {%10,%11,%12,%13};"
        : "=f"(d0), "=f"(d1), "=f"(d2), "=f"(d3)
        : "r"(a0), "r"(a1), "r"(a2), "r"(a3), "r"(b0), "r"(b1),
          "f"(c0), "f"(c1), "f"(c2), "f"(c3));
}

__device__ __forceinline__ uint32_t pack_bf16x2(float lo, float hi){
    uint32_t r;
    asm("cvt.rn.bf16x2.f32 %0, %1, %2;" : "=r"(r) : "f"(hi), "f"(lo));
    return r;
}

// ---------------- prologue: build B fragments ----------------
// window m, group g, lane: c=lane&3, n=g*8+(lane>>2), k0=16m+4c.
// slot perm: b0 = k0,k0+1 ; b1 = k0+2,k0+3 (matches A byte layout below)
__global__ void bfrag_kernel(const float* __restrict__ inp, const float* __restrict__ amax){
    int id = blockIdx.x * blockDim.x + threadIdx.x;   // 0..65535
    int lane = id & 31;
    int g    = (id >> 5) & 3;
    int m    = id >> 7;
    int c    = lane & 3;
    int n    = g * 8 + (lane >> 2);
    int k0   = 16 * m + 4 * c;
    const float am = __ldg(amax);

    float4 a = *reinterpret_cast<const float4*>(inp + (size_t)n * KFEAT + k0);
    a.x *= am; a.y *= am; a.z *= am; a.w *= am;

    uint32_t bhi0 = pack_bf16x2(a.x, a.y);
    uint32_t bhi1 = pack_bf16x2(a.z, a.w);
    float r0 = a.x - __uint_as_float(bhi0 << 16);
    float r1 = a.y - __uint_as_float(bhi0 & 0xFFFF0000u);
    float r2 = a.z - __uint_as_float(bhi1 << 16);
    float r3 = a.w - __uint_as_float(bhi1 & 0xFFFF0000u);
    uint32_t blo0 = pack_bf16x2(r0, r1);
    uint32_t blo1 = pack_bf16x2(r2, r3);

    g_bfrag[id] = make_uint4(bhi0, bhi1, blo0, blo1);
}

// ---------------- main GEMM ----------------
// CTA: 128 thr = 4 warps; warp = 32 weight rows x 32 tokens.
// grid = (NFEAT/128, KSPLIT) = (64, 8) = 512 CTAs -> one full wave @ occ 4.
__global__ void __launch_bounds__(128, 4) fp4_hmma_kernel(
    const int*   __restrict__ qw,       // [N, K/2] one packed byte per int32
    const float* __restrict__ scales)   // [N, K/16]
{
    const int tid = threadIdx.x, wid = tid >> 5, lane = tid & 31;
    const int c  = lane & 3;
    const int r0 = blockIdx.x * 128 + wid * 32 + (lane >> 2);   // rows r0, +8, +16, +24
    const int wb = blockIdx.y * WIN_PER_CTA;

    float acc[4][8];
    #pragma unroll
    for (int g = 0; g < 4; ++g)
        #pragma unroll
        for (int j = 0; j < 8; ++j) acc[g][j] = 0.f;

    const uint2* qr0 = reinterpret_cast<const uint2*>(qw + (size_t)(r0     ) * (KFEAT / 2));
    const uint2* qr1 = reinterpret_cast<const uint2*>(qw + (size_t)(r0 +  8) * (KFEAT / 2));
    const uint2* qr2 = reinterpret_cast<const uint2*>(qw + (size_t)(r0 + 16) * (KFEAT / 2));
    const uint2* qr3 = reinterpret_cast<const uint2*>(qw + (size_t)(r0 + 24) * (KFEAT / 2));
    const float* sr0 = scales + (size_t)(r0     ) * NWIN;
    const float* sr1 = scales + (size_t)(r0 +  8) * NWIN;
    const float* sr2 = scales + (size_t)(r0 + 16) * NWIN;
    const float* sr3 = scales + (size_t)(r0 + 24) * NWIN;

    for (int it = 0; it < WIN_PER_CTA / 4; ++it){
        const int mb = wb + it * 4;
        const float4 s0 = __ldg(reinterpret_cast<const float4*>(sr0 + mb));
        const float4 s1 = __ldg(reinterpret_cast<const float4*>(sr1 + mb));
        const float4 s2 = __ldg(reinterpret_cast<const float4*>(sr2 + mb));
        const float4 s3 = __ldg(reinterpret_cast<const float4*>(sr3 + mb));
        const float s0a[4] = {s0.x, s0.y, s0.z, s0.w};
        const float s1a[4] = {s1.x, s1.y, s1.z, s1.w};
        const float s2a[4] = {s2.x, s2.y, s2.z, s2.w};
        const float s3a[4] = {s3.x, s3.y, s3.z, s3.w};

        #pragma unroll
        for (int w = 0; w < 4; ++w){
            const int m = mb + w;
            // A fragments: byte pairs 8m+2c (slot c), 8m+2c+1 (slot c+4)
            const uint2 q0 = __ldg(qr0 + m * 4 + c);
            const uint2 q1 = __ldg(qr1 + m * 4 + c);
            const uint2 q2 = __ldg(qr2 + m * 4 + c);
            const uint2 q3 = __ldg(qr3 + m * 4 + c);
            const uint32_t a00 = dec(q0.x), a02 = dec(q0.y);  // rowpair0 lo-row
            const uint32_t a01 = dec(q1.x), a03 = dec(q1.y);  // rowpair0 hi-row
            const uint32_t a10 = dec(q2.x), a12 = dec(q2.y);  // rowpair1 lo-row
            const uint32_t a11 = dec(q3.x), a13 = dec(q3.y);  // rowpair1 hi-row

            #pragma unroll
            for (int g = 0; g < 4; ++g){
                const uint4 bf = __ldg(&g_bfrag[(size_t)(m * 4 + g) * 32 + lane]);
                float p0, p1, p2, p3;
                mma16816(p0, p1, p2, p3, a00, a01, a02, a03, bf.x, bf.y, 0.f, 0.f, 0.f, 0.f);
                mma16816(p0, p1, p2, p3, a00, a01, a02, a03, bf.z, bf.w, p0, p1, p2, p3);
                acc[g][0] = fmaf(s0a[w], p0, acc[g][0]);
                acc[g][1] = fmaf(s0a[w], p1, acc[g][1]);
                acc[g][2] = fmaf(s1a[w], p2, acc[g][2]);
                acc[g][3] = fmaf(s1a[w], p3, acc[g][3]);
                mma16816(p0, p1, p2, p3, a10, a11, a12, a13, bf.x, bf.y, 0.f, 0.f, 0.f, 0.f);
                mma16816(p0, p1, p2, p3, a10, a11, a12, a13, bf.z, bf.w, p0, p1, p2, p3);
                acc[g][4] = fmaf(s2a[w], p0, acc[g][4]);
                acc[g][5] = fmaf(s2a[w], p1, acc[g][5]);
                acc[g][6] = fmaf(s3a[w], p2, acc[g][6]);
                acc[g][7] = fmaf(s3a[w], p3, acc[g][7]);
            }
        }
    }

    // epilogue: token cols g*8+2c, 2c+1 ; rows r0, r0+8, r0+16, r0+24
    float* base = g_part + (size_t)blockIdx.y * (TOKENS * NFEAT);
    #pragma unroll
    for (int g = 0; g < 4; ++g){
        const int t0 = g * 8 + 2 * c;
        base[(size_t)t0       * NFEAT + r0     ] = acc[g][0];
        base[(size_t)(t0 + 1) * NFEAT + r0     ] = acc[g][1];
        base[(size_t)t0       * NFEAT + r0 +  8] = acc[g][2];
        base[(size_t)(t0 + 1) * NFEAT + r0 +  8] = acc[g][3];
        base[(size_t)t0       * NFEAT + r0 + 16] = acc[g][4];
        base[(size_t)(t0 + 1) * NFEAT + r0 + 16] = acc[g][5];
        base[(size_t)t0       * NFEAT + r0 + 24] = acc[g][6];
        base[(size_t)(t0 + 1) * NFEAT + r0 + 24] = acc[g][7];
    }
}

// ---------------- reduce split-K + bias ----------------
__global__ void reduce_kernel(const float* __restrict__ bias, float* __restrict__ out){
    int i = blockIdx.x * blockDim.x + threadIdx.x;
    if (i >= TOKENS * NFEAT) return;
    float s = bias[i & (NFEAT - 1)];
    #pragma unroll
    for (int cpart = 0; cpart < KSPLIT; ++cpart)
        s += g_part[(size_t)cpart * (TOKENS * NFEAT) + i];
    out[i] = s;
}

extern "C" void kernel_launch(void* const* d_in, const int* in_sizes, int n_in,
                              void* d_out, int out_size)
{
    const float* inp    = (const float*)d_in[0];
    const int*   qw     = (const int*)  d_in[1];
    const float* scales = (const float*)d_in[2];
    const float* amax   = (const float*)d_in[3];
    const float* bias   = (const float*)d_in[4];
    float* out = (float*)d_out;

    bfrag_kernel<<<(NWIN * 4 * 32) / 256, 256>>>(inp, amax);

    dim3 grid(NFEAT / 128, KSPLIT);
    fp4_hmma_kernel<<<grid, 128>>>(qw, scales);

    reduce_kernel<<<(TOKENS * NFEAT + 255) / 256, 256>>>(bias, out);
}

// round 5
// speedup vs baseline: 3.9664x; 1.3091x over previous
#include <cuda_runtime.h>
#include <cuda_fp16.h>
#include <cstdint>

// FP4(E2M1) weight-only linear via single-pass fp16 mma.sync HMMA.
// out[32,8192] = inp[32,8192] @ W[8192,8192]^T + bias,  W[n,k]=LUT(nib)*scales[n,k/16]*amax
// MMA uses EXACT fp16 LUT values (unscaled) x fp16(amax-folded activations);
// per-16k-block scale applied in fp32 FFMA. fp16 mantissa (10b) keeps output
// norm rel-err ~3e-4, under the 1e-3 threshold.

#define TOKENS   32
#define NFEAT    8192
#define KFEAT    8192
#define NWIN     (KFEAT / 16)          // 512 mma k-steps == scale blocks
#define KSPLIT   8
#define WIN_PER_CTA (NWIN / KSPLIT)    // 64

__device__ uint2 g_bfrag[NWIN * 4 * 32];            // [win][group][lane] {b0,b1} fp16x2
__device__ float g_part[KSPLIT * TOKENS * NFEAT];   // split-K partials (8 MB)

// decode packed byte -> fp16x2 {lut[hi nib] | lut[lo nib]} (exact, unscaled)
// fp16 codes: 0,0.5,1,1.5,2,3,4,6 -> hi bytes {00,38,3C,3E,40,42,44,46}, lo bytes 0
__device__ __forceinline__ uint32_t dec16(uint32_t b){
    uint32_t h = __byte_perm(0x3E3C3800u, 0x46444240u, b & 0x77u); // [lut_lo, lut_hi, 0, 0]
    uint32_t r = __byte_perm(h, 0u, 0x1404u);                      // [0, lut_lo, 0, lut_hi]
    return r | ((b & 0x8u) << 12) | ((b & 0x80u) << 24);           // signs -> bits 15, 31
}

__device__ __forceinline__ void mma16816(
    float& d0, float& d1, float& d2, float& d3,
    uint32_t a0, uint32_t a1, uint32_t a2, uint32_t a3,
    uint32_t b0, uint32_t b1,
    float c0, float c1, float c2, float c3)
{
    asm("mma.sync.aligned.m16n8k16.row.col.f32.f16.f16.f32 "
        "{%0,%1,%2,%3}, {%4,%5,%6,%7}, {%8,%9}, {%10,%11,%12,%13};"
        : "=f"(d0), "=f"(d1), "=f"(d2), "=f"(d3)
        : "r"(a0), "r"(a1), "r"(a2), "r"(a3), "r"(b0), "r"(b1),
          "f"(c0), "f"(c1), "f"(c2), "f"(c3));
}

__device__ __forceinline__ uint32_t pack_f16x2(float lo, float hi){
    uint32_t r;
    asm("cvt.rn.f16x2.f32 %0, %1, %2;" : "=r"(r) : "f"(hi), "f"(lo));
    return r;
}

// ---------------- prologue: build fp16 B fragments ----------------
// window m, group g, lane: c=lane&3, n=g*8+(lane>>2), k0=16m+4c.
// slot perm matches A byte order: b0 = k0,k0+1 ; b1 = k0+2,k0+3.
__global__ void bfrag_kernel(const float* __restrict__ inp, const float* __restrict__ amax){
    int id = blockIdx.x * blockDim.x + threadIdx.x;   // 0..65535
    int lane = id & 31;
    int g    = (id >> 5) & 3;
    int m    = id >> 7;
    int c    = lane & 3;
    int n    = g * 8 + (lane >> 2);
    int k0   = 16 * m + 4 * c;
    const float am = __ldg(amax);

    float4 a = *reinterpret_cast<const float4*>(inp + (size_t)n * KFEAT + k0);
    g_bfrag[id] = make_uint2(pack_f16x2(a.x * am, a.y * am),
                             pack_f16x2(a.z * am, a.w * am));
}

// ---------------- main GEMM ----------------
// CTA: 128 thr = 4 warps; warp = 32 weight rows x 32 tokens.
// grid = (NFEAT/128, KSPLIT) = (64, 8) = 512 CTAs.
__global__ void __launch_bounds__(128, 4) fp4_hmma_kernel(
    const int*   __restrict__ qw,       // [N, K/2] one packed byte per int32
    const float* __restrict__ scales)   // [N, K/16]
{
    const int tid = threadIdx.x, wid = tid >> 5, lane = tid & 31;
    const int c  = lane & 3;
    const int r0 = blockIdx.x * 128 + wid * 32 + (lane >> 2);   // rows r0, +8, +16, +24
    const int wb = blockIdx.y * WIN_PER_CTA;

    float acc[4][8];
    #pragma unroll
    for (int g = 0; g < 4; ++g)
        #pragma unroll
        for (int j = 0; j < 8; ++j) acc[g][j] = 0.f;

    const uint2* qr0 = reinterpret_cast<const uint2*>(qw + (size_t)(r0     ) * (KFEAT / 2));
    const uint2* qr1 = reinterpret_cast<const uint2*>(qw + (size_t)(r0 +  8) * (KFEAT / 2));
    const uint2* qr2 = reinterpret_cast<const uint2*>(qw + (size_t)(r0 + 16) * (KFEAT / 2));
    const uint2* qr3 = reinterpret_cast<const uint2*>(qw + (size_t)(r0 + 24) * (KFEAT / 2));
    const float* sr0 = scales + (size_t)(r0     ) * NWIN;
    const float* sr1 = scales + (size_t)(r0 +  8) * NWIN;
    const float* sr2 = scales + (size_t)(r0 + 16) * NWIN;
    const float* sr3 = scales + (size_t)(r0 + 24) * NWIN;

    for (int it = 0; it < WIN_PER_CTA / 4; ++it){
        const int mb = wb + it * 4;
        const float4 s0 = __ldg(reinterpret_cast<const float4*>(sr0 + mb));
        const float4 s1 = __ldg(reinterpret_cast<const float4*>(sr1 + mb));
        const float4 s2 = __ldg(reinterpret_cast<const float4*>(sr2 + mb));
        const float4 s3 = __ldg(reinterpret_cast<const float4*>(sr3 + mb));
        const float s0a[4] = {s0.x, s0.y, s0.z, s0.w};
        const float s1a[4] = {s1.x, s1.y, s1.z, s1.w};
        const float s2a[4] = {s2.x, s2.y, s2.z, s2.w};
        const float s3a[4] = {s3.x, s3.y, s3.z, s3.w};

        #pragma unroll
        for (int w = 0; w < 4; ++w){
            const int m = mb + w;
            // A fragments: byte pairs 8m+2c (slot c), 8m+2c+1 (slot c+4)
            const uint2 q0 = __ldg(qr0 + m * 4 + c);
            const uint2 q1 = __ldg(qr1 + m * 4 + c);
            const uint2 q2 = __ldg(qr2 + m * 4 + c);
            const uint2 q3 = __ldg(qr3 + m * 4 + c);
            const uint32_t a00 = dec16(q0.x), a02 = dec16(q0.y);  // rowpair0 lo-row
            const uint32_t a01 = dec16(q1.x), a03 = dec16(q1.y);  // rowpair0 hi-row
            const uint32_t a10 = dec16(q2.x), a12 = dec16(q2.y);  // rowpair1 lo-row
            const uint32_t a11 = dec16(q3.x), a13 = dec16(q3.y);  // rowpair1 hi-row

            #pragma unroll
            for (int g = 0; g < 4; ++g){
                const uint2 bf = __ldg(&g_bfrag[(size_t)(m * 4 + g) * 32 + lane]);
                float p0, p1, p2, p3;
                mma16816(p0, p1, p2, p3, a00, a01, a02, a03, bf.x, bf.y, 0.f, 0.f, 0.f, 0.f);
                acc[g][0] = fmaf(s0a[w], p0, acc[g][0]);
                acc[g][1] = fmaf(s0a[w], p1, acc[g][1]);
                acc[g][2] = fmaf(s1a[w], p2, acc[g][2]);
                acc[g][3] = fmaf(s1a[w], p3, acc[g][3]);
                mma16816(p0, p1, p2, p3, a10, a11, a12, a13, bf.x, bf.y, 0.f, 0.f, 0.f, 0.f);
                acc[g][4] = fmaf(s2a[w], p0, acc[g][4]);
                acc[g][5] = fmaf(s2a[w], p1, acc[g][5]);
                acc[g][6] = fmaf(s3a[w], p2, acc[g][6]);
                acc[g][7] = fmaf(s3a[w], p3, acc[g][7]);
            }
        }
    }

    // epilogue: token cols g*8+2c, 2c+1 ; rows r0, r0+8, r0+16, r0+24
    float* base = g_part + (size_t)blockIdx.y * (TOKENS * NFEAT);
    #pragma unroll
    for (int g = 0; g < 4; ++g){
        const int t0 = g * 8 + 2 * c;
        base[(size_t)t0       * NFEAT + r0     ] = acc[g][0];
        base[(size_t)(t0 + 1) * NFEAT + r0     ] = acc[g][1];
        base[(size_t)t0       * NFEAT + r0 +  8] = acc[g][2];
        base[(size_t)(t0 + 1) * NFEAT + r0 +  8] = acc[g][3];
        base[(size_t)t0       * NFEAT + r0 + 16] = acc[g][4];
        base[(size_t)(t0 + 1) * NFEAT + r0 + 16] = acc[g][5];
        base[(size_t)t0       * NFEAT + r0 + 24] = acc[g][6];
        base[(size_t)(t0 + 1) * NFEAT + r0 + 24] = acc[g][7];
    }
}

// ---------------- reduce split-K + bias ----------------
__global__ void reduce_kernel(const float* __restrict__ bias, float* __restrict__ out){
    int i = blockIdx.x * blockDim.x + threadIdx.x;
    if (i >= TOKENS * NFEAT) return;
    float s = bias[i & (NFEAT - 1)];
    #pragma unroll
    for (int cpart = 0; cpart < KSPLIT; ++cpart)
        s += g_part[(size_t)cpart * (TOKENS * NFEAT) + i];
    out[i] = s;
}

extern "C" void kernel_launch(void* const* d_in, const int* in_sizes, int n_in,
                              void* d_out, int out_size)
{
    const float* inp    = (const float*)d_in[0];
    const int*   qw     = (const int*)  d_in[1];
    const float* scales = (const float*)d_in[2];
    const float* amax   = (const float*)d_in[3];
    const float* bias   = (const float*)d_in[4];
    float* out = (float*)d_out;

    bfrag_kernel<<<(NWIN * 4 * 32) / 256, 256>>>(inp, amax);

    dim3 grid(NFEAT / 128, KSPLIT);
    fp4_hmma_kernel<<<grid, 128>>>(qw, scales);

    reduce_kernel<<<(TOKENS * NFEAT + 255) / 256, 256>>>(bias, out);
}

// round 6
// speedup vs baseline: 4.8304x; 1.2178x over previous
#include <cuda_runtime.h>
#include <cuda_fp16.h>
#include <cstdint>

// FP4(E2M1) weight-only linear, single-pass fp16 mma.sync, scales folded into
// fp16 A registers (per-register block scale), direct fp32 MMA accumulation.
// out[32,8192] = inp[32,8192] @ W[8192,8192]^T + bias
// W[n,k] = LUT(nib) * scales[n,k/16] * amax   (amax folded into activations)

#define TOKENS   32
#define NFEAT    8192
#define KFEAT    8192
#define NWIN     (KFEAT / 16)          // 512 mma k-steps
#define NMP      (NWIN / 2)            // 256 window-pairs
#define KSPLIT   8
#define WIN_PER_CTA (NWIN / KSPLIT)    // 64
#define MP_PER_CTA  (WIN_PER_CTA / 2)  // 32

__device__ uint4 g_bfrag[NMP * 4 * 32];             // [mp][g][lane] fp16x2 x4 (e0:b0,b1, e1:b0,b1)
__device__ float g_part[KSPLIT * TOKENS * NFEAT];   // split-K partials (8 MB)

// decode packed byte -> fp16x2 {lut[hi nib] | lut[lo nib]} (exact, unscaled)
__device__ __forceinline__ uint32_t dec16(uint32_t b){
    uint32_t h = __byte_perm(0x3E3C3800u, 0x46444240u, b & 0x77u);
    uint32_t r = __byte_perm(h, 0u, 0x1404u);
    return r | ((b & 0x8u) << 12) | ((b & 0x80u) << 24);
}
__device__ __forceinline__ uint32_t hmul2(uint32_t a, uint32_t b){
    uint32_t r;
    asm("mul.rn.f16x2 %0, %1, %2;" : "=r"(r) : "r"(a), "r"(b));
    return r;
}
__device__ __forceinline__ uint32_t dup_f16(float s){
    uint32_t r;
    asm("cvt.rn.f16x2.f32 %0, %1, %1;" : "=r"(r) : "f"(s));
    return r;
}
__device__ __forceinline__ uint32_t pack_f16x2(float lo, float hi){
    uint32_t r;
    asm("cvt.rn.f16x2.f32 %0, %1, %2;" : "=r"(r) : "f"(hi), "f"(lo));
    return r;
}
// accumulate in place: D = A*B + D (fp32 C/D)
__device__ __forceinline__ void mma_acc(
    float& d0, float& d1, float& d2, float& d3,
    uint32_t a0, uint32_t a1, uint32_t a2, uint32_t a3,
    uint32_t b0, uint32_t b1)
{
    asm("mma.sync.aligned.m16n8k16.row.col.f32.f16.f16.f32 "
        "{%0,%1,%2,%3}, {%4,%5,%6,%7}, {%8,%9}, {%0,%1,%2,%3};"
        : "+f"(d0), "+f"(d1), "+f"(d2), "+f"(d3)
        : "r"(a0), "r"(a1), "r"(a2), "r"(a3), "r"(b0), "r"(b1));
}

// ---------------- prologue: build fp16 B fragments ----------------
// mp = window pair, g = token group, lane: c=lane&3, n=g*8+(lane>>2).
// Lane c covers k0 = 32*mp + 8*c .. k0+7 (8 consecutive k):
//   e0: b0=(k0,k0+1) b1=(k0+2,k0+3);  e1: b0=(k0+4,k0+5) b1=(k0+6,k0+7)
__global__ void bfrag_kernel(const float* __restrict__ inp, const float* __restrict__ amax){
    int id = blockIdx.x * blockDim.x + threadIdx.x;   // 0..32767
    int lane = id & 31;
    int g    = (id >> 5) & 3;
    int mp   = id >> 7;
    int c    = lane & 3;
    int n    = g * 8 + (lane >> 2);
    int k0   = 32 * mp + 8 * c;
    const float am = __ldg(amax);

    float4 a = *reinterpret_cast<const float4*>(inp + (size_t)n * KFEAT + k0);
    float4 b = *reinterpret_cast<const float4*>(inp + (size_t)n * KFEAT + k0 + 4);
    g_bfrag[id] = make_uint4(pack_f16x2(a.x * am, a.y * am),
                             pack_f16x2(a.z * am, a.w * am),
                             pack_f16x2(b.x * am, b.y * am),
                             pack_f16x2(b.z * am, b.w * am));
}

// ---------------- main GEMM ----------------
// CTA: 128 thr = 4 warps; warp = 32 weight rows x 32 tokens.
// grid = (64, KSPLIT=8) = 512 CTAs, occ 4.
// Per mp, lane quad-pos c loads qw uint4 = payload pairs 16mp+4c..+3.
// Its 4 k-values per register all lie in scale block 2mp+(c>>1).
__global__ void __launch_bounds__(128, 4) fp4_hmma_kernel(
    const int*   __restrict__ qw,       // [N, K/2] one packed byte per int32
    const float* __restrict__ scales)   // [N, K/16]
{
    const int tid = threadIdx.x, wid = tid >> 5, lane = tid & 31;
    const int c  = lane & 3;
    const int r0 = blockIdx.x * 128 + wid * 32 + (lane >> 2);   // rows r0,+8,+16,+24
    const int mpb = blockIdx.y * MP_PER_CTA;

    float acc[4][8];
    #pragma unroll
    for (int g = 0; g < 4; ++g)
        #pragma unroll
        for (int j = 0; j < 8; ++j) acc[g][j] = 0.f;

    const uint4* qr0 = reinterpret_cast<const uint4*>(qw + (size_t)(r0     ) * (KFEAT / 2)) + c;
    const uint4* qr1 = reinterpret_cast<const uint4*>(qw + (size_t)(r0 +  8) * (KFEAT / 2)) + c;
    const uint4* qr2 = reinterpret_cast<const uint4*>(qw + (size_t)(r0 + 16) * (KFEAT / 2)) + c;
    const uint4* qr3 = reinterpret_cast<const uint4*>(qw + (size_t)(r0 + 24) * (KFEAT / 2)) + c;
    const float2* sr0 = reinterpret_cast<const float2*>(scales + (size_t)(r0     ) * NWIN);
    const float2* sr1 = reinterpret_cast<const float2*>(scales + (size_t)(r0 +  8) * NWIN);
    const float2* sr2 = reinterpret_cast<const float2*>(scales + (size_t)(r0 + 16) * NWIN);
    const float2* sr3 = reinterpret_cast<const float2*>(scales + (size_t)(r0 + 24) * NWIN);
    const bool hiblk = (lane & 2) != 0;   // c>>1

    #pragma unroll 4
    for (int mpl = 0; mpl < MP_PER_CTA; ++mpl){
        const int mp = mpb + mpl;

        const uint4 q0 = __ldg(qr0 + mp * 4);
        const uint4 q1 = __ldg(qr1 + mp * 4);
        const uint4 q2 = __ldg(qr2 + mp * 4);
        const uint4 q3 = __ldg(qr3 + mp * 4);

        const float2 t0 = __ldg(sr0 + mp);
        const float2 t1 = __ldg(sr1 + mp);
        const float2 t2 = __ldg(sr2 + mp);
        const float2 t3 = __ldg(sr3 + mp);
        const uint32_t h0 = dup_f16(hiblk ? t0.y : t0.x);
        const uint32_t h1 = dup_f16(hiblk ? t1.y : t1.x);
        const uint32_t h2 = dup_f16(hiblk ? t2.y : t2.x);
        const uint32_t h3 = dup_f16(hiblk ? t3.y : t3.x);

        uint4 bf[4];
        #pragma unroll
        for (int g = 0; g < 4; ++g)
            bf[g] = __ldg(&g_bfrag[(size_t)(mp * 4 + g) * 32 + lane]);

        // ---- e = 0 ----
        {
            const uint32_t a00 = hmul2(dec16(q0.x), h0), a02 = hmul2(dec16(q0.y), h0);
            const uint32_t a01 = hmul2(dec16(q1.x), h1), a03 = hmul2(dec16(q1.y), h1);
            const uint32_t a10 = hmul2(dec16(q2.x), h2), a12 = hmul2(dec16(q2.y), h2);
            const uint32_t a11 = hmul2(dec16(q3.x), h3), a13 = hmul2(dec16(q3.y), h3);
            #pragma unroll
            for (int g = 0; g < 4; ++g){
                mma_acc(acc[g][0], acc[g][1], acc[g][2], acc[g][3],
                        a00, a01, a02, a03, bf[g].x, bf[g].y);
                mma_acc(acc[g][4], acc[g][5], acc[g][6], acc[g][7],
                        a10, a11, a12, a13, bf[g].x, bf[g].y);
            }
        }
        // ---- e = 1 ----
        {
            const uint32_t a00 = hmul2(dec16(q0.z), h0), a02 = hmul2(dec16(q0.w), h0);
            const uint32_t a01 = hmul2(dec16(q1.z), h1), a03 = hmul2(dec16(q1.w), h1);
            const uint32_t a10 = hmul2(dec16(q2.z), h2), a12 = hmul2(dec16(q2.w), h2);
            const uint32_t a11 = hmul2(dec16(q3.z), h3), a13 = hmul2(dec16(q3.w), h3);
            #pragma unroll
            for (int g = 0; g < 4; ++g){
                mma_acc(acc[g][0], acc[g][1], acc[g][2], acc[g][3],
                        a00, a01, a02, a03, bf[g].z, bf[g].w);
                mma_acc(acc[g][4], acc[g][5], acc[g][6], acc[g][7],
                        a10, a11, a12, a13, bf[g].z, bf[g].w);
            }
        }
    }

    // epilogue: token cols g*8+2c, 2c+1 ; rows r0, +8, +16, +24
    float* base = g_part + (size_t)blockIdx.y * (TOKENS * NFEAT);
    #pragma unroll
    for (int g = 0; g < 4; ++g){
        const int t0c = g * 8 + 2 * c;
        base[(size_t)t0c       * NFEAT + r0     ] = acc[g][0];
        base[(size_t)(t0c + 1) * NFEAT + r0     ] = acc[g][1];
        base[(size_t)t0c       * NFEAT + r0 +  8] = acc[g][2];
        base[(size_t)(t0c + 1) * NFEAT + r0 +  8] = acc[g][3];
        base[(size_t)t0c       * NFEAT + r0 + 16] = acc[g][4];
        base[(size_t)(t0c + 1) * NFEAT + r0 + 16] = acc[g][5];
        base[(size_t)t0c       * NFEAT + r0 + 24] = acc[g][6];
        base[(size_t)(t0c + 1) * NFEAT + r0 + 24] = acc[g][7];
    }
}

// ---------------- reduce split-K + bias ----------------
__global__ void reduce_kernel(const float* __restrict__ bias, float* __restrict__ out){
    int i = blockIdx.x * blockDim.x + threadIdx.x;
    if (i >= TOKENS * NFEAT) return;
    float s = bias[i & (NFEAT - 1)];
    #pragma unroll
    for (int cp = 0; cp < KSPLIT; ++cp)
        s += g_part[(size_t)cp * (TOKENS * NFEAT) + i];
    out[i] = s;
}

extern "C" void kernel_launch(void* const* d_in, const int* in_sizes, int n_in,
                              void* d_out, int out_size)
{
    const float* inp    = (const float*)d_in[0];
    const int*   qw     = (const int*)  d_in[1];
    const float* scales = (const float*)d_in[2];
    const float* amax   = (const float*)d_in[3];
    const float* bias   = (const float*)d_in[4];
    float* out = (float*)d_out;

    bfrag_kernel<<<(NMP * 4 * 32) / 256, 256>>>(inp, amax);

    dim3 grid(NFEAT / 128, KSPLIT);
    fp4_hmma_kernel<<<grid, 128>>>(qw, scales);

    reduce_kernel<<<(TOKENS * NFEAT + 255) / 256, 256>>>(bias, out);
}